// round 13
// baseline (speedup 1.0000x reference)
#include <cuda_runtime.h>
#include <math.h>

#define NBITS   20
#define NSUB    ((1u << NBITS) - 1u)    // 1048575 elements in w
#define NT16    (1 << (NBITS - 4))      // 65536 threads, 16 elements each
#define NBLK    256
#define NTPB    256
#define NWARP   (NTPB / 32)
#define FULLM   0xFFFFFFFFu

// Cross-block scalar accumulator + arrival counter. Both are reset by the
// final block every launch -> deterministic across graph replays.
__device__ float        g_acc   = 0.0f;
__device__ unsigned int g_count = 0;

__global__ void __launch_bounds__(NTPB) mil_main_kernel(const float* __restrict__ w,
                                                        const float* __restrict__ yprob,
                                                        const int*   __restrict__ Yp,
                                                        int has_Y,
                                                        float* __restrict__ out) {
    const int tid  = threadIdx.x;
    const int warp = tid >> 5;
    const int lane = tid & 31;
    const int t    = blockIdx.x * NTPB + tid;   // chunk id, 0..65535 (exact cover)
    const int e0   = t << 4;                    // first element index of this chunk

    // ---- issue all 4 LDG.128 first; latency hides the coefficient setup ----
    float v[16];
    const float4* __restrict__ w4 = (const float4*)w;
    if (t != NT16 - 1) {
#pragma unroll
        for (int g = 0; g < 4; g++) {
            float4 a = w4[(e0 >> 2) + g];
            v[4*g+0]=a.x; v[4*g+1]=a.y; v[4*g+2]=a.z; v[4*g+3]=a.w;
        }
    } else {
#pragma unroll
        for (int g = 0; g < 3; g++) {
            float4 a = w4[(e0 >> 2) + g];
            v[4*g+0]=a.x; v[4*g+1]=a.y; v[4*g+2]=a.z; v[4*g+3]=a.w;
        }
        v[12] = w[e0 + 12];
        v[13] = w[e0 + 13];
        v[14] = w[e0 + 14];
        v[15] = 0.0f;                    // subset index 2^20 does not exist
    }

    // ---- warp 0 builds cf[0..20] and the low-4-bit table cl4[16] in smem ----
    __shared__ float cf[NBITS + 1];
    __shared__ float cl4[16];
    __shared__ float sp[NWARP];
    const int y_nonzero = has_Y ? (Yp[0] != 0) : 1;
    float base = 0.0f;                           // valid on warp 0 after reduce
    if (warp == 0) {
        const float pp  = (lane < NBITS) ? yprob[lane] : 0.5f;
        const float lpv = logf(pp);
        const float l1v = logf(1.0f - pp);
        const float diff = lpv - l1v;
        float b1 = (lane < NBITS) ? l1v : 0.0f;
#pragma unroll
        for (int o = 16; o > 0; o >>= 1) b1 += __shfl_xor_sync(FULLM, b1, o);
        base = b1;                               // sum of log1mp
        const int   src   = (lane < NBITS) ? (NBITS - 1 - lane) : 0;
        const float cdiff = __shfl_sync(FULLM, diff, src);
        float cv;
        if      (lane <  NBITS) cv = cdiff;
        else if (lane == NBITS) cv = base;
        else                    cv = 0.0f;
        if (!y_nonzero)         cv = 0.0f;       // Y==0: closed form added at the end
        if (lane <= NBITS) cf[lane] = cv;

        const float c0 = __shfl_sync(FULLM, cv, 0);
        const float c1 = __shfl_sync(FULLM, cv, 1);
        const float c2 = __shfl_sync(FULLM, cv, 2);
        const float c3 = __shfl_sync(FULLM, cv, 3);
        if (lane < 16) {
            float s = 0.0f;
            if (lane & 1) s += c0;
            if (lane & 2) s += c1;
            if (lane & 4) s += c2;
            if (lane & 8) s += c3;
            cl4[lane] = s;
        }
    }
    __syncthreads();

    // ---- c_high for this chunk (bits >=4 of i = bits of t) and for the
    //      boundary element (bits of t+1). t < 2^16 so 16 bits suffice;
    //      t+1 == 2^16 only when v[15] == 0, so dropping bit 16 is harmless. ----
    const unsigned ut  = (unsigned)t;
    const unsigned ut1 = ut + 1u;
    float ch  = cf[NBITS];
    float ch2 = cf[NBITS];
#pragma unroll
    for (int b = 0; b < 16; b++) {
        const float c = cf[4 + b];
        if ((ut  >> b) & 1u) ch  += c;
        if ((ut1 >> b) & 1u) ch2 += c;
    }

    // ---- per-element dot: k=0..14 -> low4 = k+1; element 15 -> low4 = 0 ----
    float a0 = 0.0f, a1 = 0.0f, a2 = 0.0f, a3 = 0.0f;
#pragma unroll
    for (int k = 0; k < 12; k += 4) {
        a0 = fmaf(v[k+0], cl4[k+1], a0);
        a1 = fmaf(v[k+1], cl4[k+2], a1);
        a2 = fmaf(v[k+2], cl4[k+3], a2);
        a3 = fmaf(v[k+3], cl4[k+4], a3);
    }
    a0 = fmaf(v[12], cl4[13], a0);
    a1 = fmaf(v[13], cl4[14], a1);
    a2 = fmaf(v[14], cl4[15], a2);

    // S15 = sum of v[0..14], clean pairwise tree
    const float s01 = v[0] + v[1],  s23 = v[2] + v[3];
    const float s45 = v[4] + v[5],  s67 = v[6] + v[7];
    const float s89 = v[8] + v[9],  sAB = v[10] + v[11];
    const float sCD = v[12] + v[13];
    const float S15 = ((s01 + s23) + (s45 + s67)) + ((s89 + sAB) + (sCD + v[14]));

    float acc = ((a0 + a1) + (a2 + a3)) + ch * S15 + ch2 * v[15];

    // ---- warp reduce, block fold ----
#pragma unroll
    for (int o = 16; o > 0; o >>= 1) acc += __shfl_xor_sync(FULLM, acc, o);
    if (lane == 0) sp[warp] = acc;
    __syncthreads();

    // ---- single-node finish: scalar atomic + last-block publish ----
    __shared__ unsigned int s_ticket;
    if (tid == 0) {
        float a = ((sp[0] + sp[1]) + (sp[2] + sp[3]))
                + ((sp[4] + sp[5]) + (sp[6] + sp[7]));
        atomicAdd(&g_acc, a);
        __threadfence();                        // order g_acc before counter
        s_ticket = atomicAdd(&g_count, 1u);
    }
    __syncthreads();
    if (tid == 0 && s_ticket == NBLK - 1) {
        __threadfence();                        // all g_acc adds visible
        float r = g_acc;
        if (!y_nonzero)
            r += (float)((double)NSUB * (double)base);
        out[0] = r;                             // single full write (poison-safe)
        g_acc   = 0.0f;                         // reset for next graph replay
        g_count = 0;
    }
}

extern "C" void kernel_launch(void* const* d_in, const int* in_sizes, int n_in,
                              void* d_out, int out_size) {
    const float* yprob = (const float*)d_in[0];
    const float* w     = (const float*)d_in[1];
    const int*   Yp    = (n_in >= 3) ? (const int*)d_in[2] : nullptr;
    float*       out   = (float*)d_out;
    (void)in_sizes; (void)out_size;

    mil_main_kernel<<<NBLK, NTPB>>>(w, yprob, Yp, Yp != nullptr ? 1 : 0, out);
}

// round 14
// speedup vs baseline: 1.0895x; 1.0895x over previous
#include <cuda_runtime.h>
#include <math.h>

#define NBITS   20
#define NSUB    ((1u << NBITS) - 1u)    // 1048575 elements in w
#define NT8     (1 << (NBITS - 3))      // 131072 threads, 8 elements each
#define NBLK    1024
#define NTPB    128
#define NWARP   (NTPB / 32)
#define FULLM   0xFFFFFFFFu

// Single pass: per-element dot with the per-subset coefficient, decomposed as
// c_i = c_low3(i & 7) + c_high(i >> 3). Coefficients built in smem by warp 0
// while every thread's 2 LDG.128 are in flight. One atomicAdd per block into
// the memset-zeroed output.
__global__ void __launch_bounds__(NTPB) mil_main_kernel(const float* __restrict__ w,
                                                        const float* __restrict__ yprob,
                                                        const int*   __restrict__ Yp,
                                                        int has_Y,
                                                        float* __restrict__ out) {
    const int tid  = threadIdx.x;
    const int warp = tid >> 5;
    const int lane = tid & 31;
    const int t    = blockIdx.x * NTPB + tid;   // chunk id, 0..131071 (exact cover)
    const int e0   = t << 3;                    // first element index of this chunk

    // ---- issue both LDG.128 first; latency hides the coefficient setup ----
    float v[8];
    const float4* __restrict__ w4 = (const float4*)w;
    if (t != NT8 - 1) {
        float4 a = w4[(e0 >> 2) + 0];
        float4 b = w4[(e0 >> 2) + 1];
        v[0]=a.x; v[1]=a.y; v[2]=a.z; v[3]=a.w;
        v[4]=b.x; v[5]=b.y; v[6]=b.z; v[7]=b.w;
    } else {
        // last chunk: e = 1048568..1048574 exist; e = 1048575 does not
        float4 a = w4[(e0 >> 2) + 0];
        v[0]=a.x; v[1]=a.y; v[2]=a.z; v[3]=a.w;
        v[4] = w[e0 + 4];
        v[5] = w[e0 + 5];
        v[6] = w[e0 + 6];
        v[7] = 0.0f;                    // subset index 2^20 does not exist
    }

    // ---- warp 0 builds cf[0..20] and the low-3-bit table cl3[8] in smem ----
    // cf[b] (b<20) = coefficient of bit b of the subset index = logp[19-b]-log1mp[19-b]
    // cf[20]       = sum_j log1mp[j]  (constant term of every c_i)
    __shared__ float cf[NBITS + 1];
    __shared__ float cl3[8];
    __shared__ float sp[NWARP];
    const int y_nonzero = has_Y ? (Yp[0] != 0) : 1;
    float base = 0.0f;                           // valid on warp 0 after reduce
    if (warp == 0) {
        const float pp  = (lane < NBITS) ? yprob[lane] : 0.5f;
        const float lpv = logf(pp);
        const float l1v = logf(1.0f - pp);
        const float diff = lpv - l1v;
        float b1 = (lane < NBITS) ? l1v : 0.0f;
#pragma unroll
        for (int o = 16; o > 0; o >>= 1) b1 += __shfl_xor_sync(FULLM, b1, o);
        base = b1;                               // sum of log1mp
        const int   src   = (lane < NBITS) ? (NBITS - 1 - lane) : 0;
        const float cdiff = __shfl_sync(FULLM, diff, src);
        float cv;
        if      (lane <  NBITS) cv = cdiff;
        else if (lane == NBITS) cv = base;
        else                    cv = 0.0f;
        if (!y_nonzero)         cv = 0.0f;       // Y==0: closed form added by block 0
        if (lane <= NBITS) cf[lane] = cv;

        const float c0 = __shfl_sync(FULLM, cv, 0);
        const float c1 = __shfl_sync(FULLM, cv, 1);
        const float c2 = __shfl_sync(FULLM, cv, 2);
        if (lane < 8) {
            float s = 0.0f;
            if (lane & 1) s += c0;
            if (lane & 2) s += c1;
            if (lane & 4) s += c2;
            cl3[lane] = s;
        }
    }
    __syncthreads();

    // ---- c_high for this chunk (bits >=3 of i = bits of t, 17 bits) and for
    //      the boundary element (bits of t+1). t+1 == 2^17 only when v[7]==0,
    //      so dropping bit 17 is harmless. ----
    const unsigned ut  = (unsigned)t;
    const unsigned ut1 = ut + 1u;
    float ch  = cf[NBITS];
    float ch2 = cf[NBITS];
#pragma unroll
    for (int b = 0; b < 17; b++) {
        const float c = cf[3 + b];
        if ((ut  >> b) & 1u) ch  += c;
        if ((ut1 >> b) & 1u) ch2 += c;
    }

    // ---- per-element dot: k=0..6 -> low3 = k+1; element 7 -> low3 = 0 ----
    float a0 = 0.0f, a1 = 0.0f, a2 = 0.0f, a3 = 0.0f;
    a0 = fmaf(v[0], cl3[1], a0);
    a1 = fmaf(v[1], cl3[2], a1);
    a2 = fmaf(v[2], cl3[3], a2);
    a3 = fmaf(v[3], cl3[4], a3);
    a0 = fmaf(v[4], cl3[5], a0);
    a1 = fmaf(v[5], cl3[6], a1);
    a2 = fmaf(v[6], cl3[7], a2);

    // S7 = sum of v[0..6], clean pairwise tree
    const float S7 = ((v[0] + v[1]) + (v[2] + v[3])) + ((v[4] + v[5]) + v[6]);

    float acc = ((a0 + a1) + (a2 + a3)) + ch * S7 + ch2 * v[7];

    // ---- warp reduce, block fold, one atomic per block ----
#pragma unroll
    for (int o = 16; o > 0; o >>= 1) acc += __shfl_xor_sync(FULLM, acc, o);
    if (lane == 0) sp[warp] = acc;
    __syncthreads();
    if (tid == 0) {
        float a = (sp[0] + sp[1]) + (sp[2] + sp[3]);
        if (!y_nonzero && blockIdx.x == 0)
            a += (float)((double)NSUB * (double)base);
        atomicAdd(out, a);
    }
}

extern "C" void kernel_launch(void* const* d_in, const int* in_sizes, int n_in,
                              void* d_out, int out_size) {
    const float* yprob = (const float*)d_in[0];
    const float* w     = (const float*)d_in[1];
    const int*   Yp    = (n_in >= 3) ? (const int*)d_in[2] : nullptr;
    float*       out   = (float*)d_out;
    (void)in_sizes; (void)out_size;

    cudaMemsetAsync(out, 0, sizeof(float));   // graph-capturable memset node
    mil_main_kernel<<<NBLK, NTPB>>>(w, yprob, Yp, Yp != nullptr ? 1 : 0, out);
}